// round 6
// baseline (speedup 1.0000x reference)
#include <cuda_runtime.h>
#include <cuda_bf16.h>

#define N_NODES 100000
#define N_EDGES 1600000
#define D 128
#define ALPHA 0.5f
#define TILE_NODES 32
#define N_TILES (N_NODES / TILE_NODES)   // 3125 exact (100000 % 32 == 0)
#define WPAD 132                          // weight row stride in words; 16B aligned;
                                          // vec4-group (33d+kg)%8 = (d+kg)%8 -> conflict-free LDS.128

// -------- static device scratch --------
__device__ float g_y_src[(size_t)N_NODES * D];   // x @ (alpha*W_src)^T        (unscaled)
__device__ float g_y_dst[(size_t)N_NODES * D];   // x @ ((1-alpha)*W_dst)^T    (unscaled)
__device__ float g_cnt_row[N_NODES], g_cnt_col[N_NODES];   // float degree counts
__device__ float g_dinv_out[N_NODES], g_dinv_in[N_NODES];  // deg^{-1/2}
__device__ int   g_is64;

__device__ __forceinline__ int ldidx(const void* p, long long i, int is64) {
  if (is64) return (int)((const long long*)p)[i];
  return ((const int*)p)[i];
}

__device__ __forceinline__ unsigned long long ffma2(
    unsigned long long a, unsigned long long b, unsigned long long c) {
  unsigned long long d;
  asm("fma.rn.f32x2 %0, %1, %2, %3;" : "=l"(d) : "l"(a), "l"(b), "l"(c));
  return d;
}
__device__ __forceinline__ float unpack_sum(unsigned long long a) {
  return __uint_as_float((unsigned)a) + __uint_as_float((unsigned)(a >> 32));
}

// -------- 1: zero degree counts + detect index dtype --------
__global__ void k_prep(const void* ei) {
  long long i = (long long)blockIdx.x * blockDim.x + threadIdx.x;
  if (i == 0) {
    const long long* p = (const long long*)ei;
    int ok = 1;
#pragma unroll
    for (int j = 0; j < 16; j++) {
      long long v = p[j];
      if (v < 0 || v >= N_NODES) ok = 0;
    }
    g_is64 = ok;   // int32 data read as int64 is out of range w.p. ~1
  }
  if (i < N_NODES) { g_cnt_row[i] = 0.f; g_cnt_col[i] = 0.f; }
}

// -------- 2: degree histograms (float atomics) --------
__global__ void k_degree(const void* ei) {
  long long e = (long long)blockIdx.x * blockDim.x + threadIdx.x;
  if (e >= N_EDGES) return;
  int is64 = g_is64;
  int r = ldidx(ei, e, is64);
  int c = ldidx(ei, (long long)N_EDGES + e, is64);
  atomicAdd(&g_cnt_row[r], 1.f);
  atomicAdd(&g_cnt_col[c], 1.f);
}

// -------- 3: transform (packed f32x2 FMAs) + bias-init of out + dinv --------
__global__ void __launch_bounds__(256, 1) k_transform(
    const float* __restrict__ x,
    const float* __restrict__ W_src, const float* __restrict__ b_src,
    const float* __restrict__ W_dst, const float* __restrict__ b_dst,
    float* __restrict__ out) {
  extern __shared__ float smem[];
  float* Ws = smem;                 // [128][WPAD] natural [d][k], scaled by ALPHA
  float* Wd = Ws + D * WPAD;        // scaled by 1-ALPHA
  float* xs = Wd + D * WPAD;        // [32 nodes][128]

  int tid = threadIdx.x;
  for (int idx = tid; idx < D * D; idx += 256) {
    int d = idx >> 7, k = idx & 127;
    Ws[d * WPAD + k] = ALPHA * W_src[idx];
    Wd[d * WPAD + k] = (1.f - ALPHA) * W_dst[idx];
  }
  int d = tid & 127;
  int half = tid >> 7;
  float bias = ALPHA * b_src[d] + (1.f - ALPHA) * b_dst[d];
  __syncthreads();

  const ulonglong2* wsp = (const ulonglong2*)(Ws + d * WPAD);
  const ulonglong2* wdp = (const ulonglong2*)(Wd + d * WPAD);

  for (int tile = blockIdx.x; tile < N_TILES; tile += gridDim.x) {
    long long base = (long long)tile * TILE_NODES;
    { // vectorized tile load: 32*128 floats = 1024 float4
      const float4* src = (const float4*)(x + base * D);
      float4* dst = (float4*)xs;
      for (int idx = tid; idx < TILE_NODES * D / 4; idx += 256) dst[idx] = src[idx];
    }
    __syncthreads();

    unsigned long long acc_s[16], acc_d[16];
#pragma unroll
    for (int i = 0; i < 16; i++) { acc_s[i] = 0ull; acc_d[i] = 0ull; }

    const ulonglong2* xrow = (const ulonglong2*)(xs + (half * 16) * D);
#pragma unroll 2
    for (int kg = 0; kg < 32; kg++) {          // 4 k per group
      ulonglong2 ws = wsp[kg];
      ulonglong2 wd = wdp[kg];
#pragma unroll
      for (int i = 0; i < 16; i++) {
        ulonglong2 xv = xrow[i * 32 + kg];     // broadcast LDS.128 (all lanes same addr)
        acc_s[i] = ffma2(xv.x, ws.x, acc_s[i]);
        acc_s[i] = ffma2(xv.y, ws.y, acc_s[i]);
        acc_d[i] = ffma2(xv.x, wd.x, acc_d[i]);
        acc_d[i] = ffma2(xv.y, wd.y, acc_d[i]);
      }
    }

#pragma unroll
    for (int i = 0; i < 16; i++) {
      long long node = base + half * 16 + i;
      g_y_src[node * D + d] = unpack_sum(acc_s[i]);
      g_y_dst[node * D + d] = unpack_sum(acc_d[i]);
      out[node * D + d] = bias;            // init out with combined bias
      if (d == 0) {
        float cr = g_cnt_row[node], cc = g_cnt_col[node];
        g_dinv_out[node] = cr > 0.f ? rsqrtf(cr) : 0.f;
        g_dinv_in[node]  = cc > 0.f ? rsqrtf(cc) : 0.f;
      }
    }
    __syncthreads();
  }
}

// -------- 4/5: split edge scatter, one warp per edge, float4 reductions --------
__device__ __forceinline__ void red_add_f4(float* p, float a, float b, float c, float d) {
  asm volatile("red.global.add.v4.f32 [%0], {%1, %2, %3, %4};"
               :: "l"(p), "f"(a), "f"(b), "f"(c), "f"(d) : "memory");
}

// forward: out[row] += w * y_src[col]       (working set: y_src + out ~ 102MB, L2-resident)
__global__ void k_scatter_fwd(const void* ei, float* __restrict__ out) {
  int lane = threadIdx.x & 31;
  long long e = (long long)blockIdx.x * 8 + (threadIdx.x >> 5);   // 1.6M % 8 == 0
  int is64 = g_is64;
  int r = ldidx(ei, e, is64);
  int c = ldidx(ei, (long long)N_EDGES + e, is64);
  float w = g_dinv_out[r] * g_dinv_in[c];
  float4 a = ((const float4*)(g_y_src + (long long)c * D))[lane];  // 512B coalesced
  red_add_f4(out + (long long)r * D + lane * 4, w * a.x, w * a.y, w * a.z, w * a.w);
}

// backward: out[col] += w * y_dst[row]
__global__ void k_scatter_bwd(const void* ei, float* __restrict__ out) {
  int lane = threadIdx.x & 31;
  long long e = (long long)blockIdx.x * 8 + (threadIdx.x >> 5);
  int is64 = g_is64;
  int r = ldidx(ei, e, is64);
  int c = ldidx(ei, (long long)N_EDGES + e, is64);
  float w = g_dinv_out[r] * g_dinv_in[c];
  float4 b = ((const float4*)(g_y_dst + (long long)r * D))[lane];
  red_add_f4(out + (long long)c * D + lane * 4, w * b.x, w * b.y, w * b.z, w * b.w);
}

// -------- launch --------
extern "C" void kernel_launch(void* const* d_in, const int* in_sizes, int n_in,
                              void* d_out, int out_size) {
  const float* x     = (const float*)d_in[0];
  const void*  ei    = d_in[1];                 // int64 or int32, auto-detected
  const float* W_src = (const float*)d_in[2];
  const float* b_src = (const float*)d_in[3];
  const float* W_dst = (const float*)d_in[4];
  const float* b_dst = (const float*)d_in[5];
  float* out = (float*)d_out;

  k_prep  <<<(N_NODES + 255) / 256, 256>>>(ei);
  k_degree<<<(N_EDGES + 255) / 256, 256>>>(ei);

  size_t smem_bytes = (size_t)(2 * D * WPAD + TILE_NODES * D) * sizeof(float);
  cudaFuncSetAttribute(k_transform, cudaFuncAttributeMaxDynamicSharedMemorySize,
                       (int)smem_bytes);
  k_transform<<<152, 256, smem_bytes>>>(x, W_src, b_src, W_dst, b_dst, out);

  k_scatter_fwd<<<N_EDGES / 8, 256>>>(ei, out);
  k_scatter_bwd<<<N_EDGES / 8, 256>>>(ei, out);
}

// round 7
// speedup vs baseline: 1.3455x; 1.3455x over previous
#include <cuda_runtime.h>
#include <cuda_fp16.h>

#define N_NODES 100000
#define N_EDGES 1600000
#define D 128
#define ALPHA 0.5f
#define TILE_NODES 32
#define N_TILES (N_NODES / TILE_NODES)   // 3125 exact
#define WPAD 132                          // conflict-free LDS.128 per quarter-warp phase

// -------- static device scratch --------
__device__ __half g_y_src[(size_t)N_NODES * D];  // dinv_in[n] * (x @ (a*Ws)^T)[n]   fp16
__device__ __half g_y_dst[(size_t)N_NODES * D];  // dinv_out[n] * (x @ ((1-a)*Wd)^T)[n]
__device__ float g_cnt_row[N_NODES], g_cnt_col[N_NODES];
__device__ float g_dinv_out[N_NODES], g_dinv_in[N_NODES];
__device__ int   g_is64;

__device__ __forceinline__ int ldidx(const void* p, long long i, int is64) {
  if (is64) return (int)((const long long*)p)[i];
  return ((const int*)p)[i];
}
__device__ __forceinline__ unsigned long long ffma2(
    unsigned long long a, unsigned long long b, unsigned long long c) {
  unsigned long long d;
  asm("fma.rn.f32x2 %0, %1, %2, %3;" : "=l"(d) : "l"(a), "l"(b), "l"(c));
  return d;
}
__device__ __forceinline__ float unpack_sum(unsigned long long a) {
  return __uint_as_float((unsigned)a) + __uint_as_float((unsigned)(a >> 32));
}

// -------- 1: zero degree counts + detect index dtype --------
__global__ void k_prep(const void* ei) {
  long long i = (long long)blockIdx.x * blockDim.x + threadIdx.x;
  if (i == 0) {
    const long long* p = (const long long*)ei;
    int ok = 1;
#pragma unroll
    for (int j = 0; j < 16; j++) {
      long long v = p[j];
      if (v < 0 || v >= N_NODES) ok = 0;
    }
    g_is64 = ok;
  }
  if (i < N_NODES) { g_cnt_row[i] = 0.f; g_cnt_col[i] = 0.f; }
}

// -------- 2: degree histograms --------
__global__ void k_degree(const void* ei) {
  long long e = (long long)blockIdx.x * blockDim.x + threadIdx.x;
  if (e >= N_EDGES) return;
  int is64 = g_is64;
  int r = ldidx(ei, e, is64);
  int c = ldidx(ei, (long long)N_EDGES + e, is64);
  atomicAdd(&g_cnt_row[r], 1.f);
  atomicAdd(&g_cnt_col[c], 1.f);
}

// -------- 3: transform, 512 thr / 8 nodes per thread, fp16 + dinv-prescaled out --------
__global__ void __launch_bounds__(512, 1) k_transform(
    const float* __restrict__ x,
    const float* __restrict__ W_src, const float* __restrict__ b_src,
    const float* __restrict__ W_dst, const float* __restrict__ b_dst,
    float* __restrict__ out) {
  extern __shared__ float smem[];
  float* Ws = smem;                 // [128][WPAD], natural [d][k], scaled by ALPHA
  float* Wd = Ws + D * WPAD;        // scaled by 1-ALPHA
  float* xs = Wd + D * WPAD;        // [32 nodes][128]

  int tid = threadIdx.x;
  for (int idx = tid; idx < D * D; idx += 512) {
    int d = idx >> 7, k = idx & 127;
    Ws[d * WPAD + k] = ALPHA * W_src[idx];
    Wd[d * WPAD + k] = (1.f - ALPHA) * W_dst[idx];
  }
  int d = tid & 127;
  int q = tid >> 7;                 // quarter: 8 nodes each
  float bias = ALPHA * b_src[d] + (1.f - ALPHA) * b_dst[d];
  __syncthreads();

  const ulonglong2* wsp = (const ulonglong2*)(Ws + d * WPAD);
  const ulonglong2* wdp = (const ulonglong2*)(Wd + d * WPAD);

  for (int tile = blockIdx.x; tile < N_TILES; tile += gridDim.x) {
    long long base = (long long)tile * TILE_NODES;
    {
      const float4* src = (const float4*)(x + base * D);
      float4* dst = (float4*)xs;
      for (int idx = tid; idx < TILE_NODES * D / 4; idx += 512) dst[idx] = src[idx];
    }
    __syncthreads();

    unsigned long long acc_s[8], acc_d[8];
#pragma unroll
    for (int i = 0; i < 8; i++) { acc_s[i] = 0ull; acc_d[i] = 0ull; }

    const ulonglong2* xrow = (const ulonglong2*)(xs + (q * 8) * D);
#pragma unroll 4
    for (int kg = 0; kg < 32; kg++) {          // 4 k per group
      ulonglong2 ws = wsp[kg];
      ulonglong2 wd = wdp[kg];
#pragma unroll
      for (int i = 0; i < 8; i++) {
        ulonglong2 xv = xrow[i * 32 + kg];     // broadcast LDS.128
        acc_s[i] = ffma2(xv.x, ws.x, acc_s[i]);
        acc_s[i] = ffma2(xv.y, ws.y, acc_s[i]);
        acc_d[i] = ffma2(xv.x, wd.x, acc_d[i]);
        acc_d[i] = ffma2(xv.y, wd.y, acc_d[i]);
      }
    }

#pragma unroll
    for (int i = 0; i < 8; i++) {
      long long node = base + q * 8 + i;
      float cr = g_cnt_row[node], cc = g_cnt_col[node];   // L2-hot after k_degree
      float dout = cr > 0.f ? rsqrtf(cr) : 0.f;
      float di   = cc > 0.f ? rsqrtf(cc) : 0.f;
      // pre-scale: y_src carries its col-side factor, y_dst its row-side factor
      g_y_src[node * D + d] = __float2half_rn(di   * unpack_sum(acc_s[i]));
      g_y_dst[node * D + d] = __float2half_rn(dout * unpack_sum(acc_d[i]));
      out[node * D + d] = bias;
      if (d == 0) { g_dinv_out[node] = dout; g_dinv_in[node] = di; }
    }
    __syncthreads();
  }
}

// -------- 4: combined edge scatter, one warp per edge --------
__device__ __forceinline__ void red_add_f4(float* p, float a, float b, float c, float d) {
  asm volatile("red.global.add.v4.f32 [%0], {%1, %2, %3, %4};"
               :: "l"(p), "f"(a), "f"(b), "f"(c), "f"(d) : "memory");
}

__global__ void k_scatter(const void* ei, float* __restrict__ out) {
  int lane = threadIdx.x & 31;
  long long e = (long long)blockIdx.x * 8 + (threadIdx.x >> 5);   // 1.6M % 8 == 0
  int is64 = g_is64;
  int r = ldidx(ei, e, is64);
  int c = ldidx(ei, (long long)N_EDGES + e, is64);
  float wr = g_dinv_out[r];     // fwd weight remainder (col factor folded into y_src)
  float wc = g_dinv_in[c];      // bwd weight remainder (row factor folded into y_dst)

  // fwd: out[row] += dinv_out[r] * y_src'[col]
  uint2 a = ((const uint2*)g_y_src)[(long long)c * 32 + lane];    // 4 halves, 256B/warp
  float2 a0 = __half22float2(*(const __half2*)&a.x);
  float2 a1 = __half22float2(*(const __half2*)&a.y);
  red_add_f4(out + (long long)r * D + lane * 4,
             wr * a0.x, wr * a0.y, wr * a1.x, wr * a1.y);

  // bwd: out[col] += dinv_in[c] * y_dst'[row]
  uint2 b = ((const uint2*)g_y_dst)[(long long)r * 32 + lane];
  float2 b0 = __half22float2(*(const __half2*)&b.x);
  float2 b1 = __half22float2(*(const __half2*)&b.y);
  red_add_f4(out + (long long)c * D + lane * 4,
             wc * b0.x, wc * b0.y, wc * b1.x, wc * b1.y);
}

// -------- launch --------
extern "C" void kernel_launch(void* const* d_in, const int* in_sizes, int n_in,
                              void* d_out, int out_size) {
  const float* x     = (const float*)d_in[0];
  const void*  ei    = d_in[1];
  const float* W_src = (const float*)d_in[2];
  const float* b_src = (const float*)d_in[3];
  const float* W_dst = (const float*)d_in[4];
  const float* b_dst = (const float*)d_in[5];
  float* out = (float*)d_out;

  k_prep  <<<(N_NODES + 255) / 256, 256>>>(ei);
  k_degree<<<(N_EDGES + 255) / 256, 256>>>(ei);

  size_t smem_bytes = (size_t)(2 * D * WPAD + TILE_NODES * D) * sizeof(float);
  cudaFuncSetAttribute(k_transform, cudaFuncAttributeMaxDynamicSharedMemorySize,
                       (int)smem_bytes);
  k_transform<<<152, 512, smem_bytes>>>(x, W_src, b_src, W_dst, b_dst, out);

  k_scatter<<<N_EDGES / 8, 256>>>(ei, out);
}

// round 9
// speedup vs baseline: 1.5046x; 1.1182x over previous
#include <cuda_runtime.h>
#include <cuda_fp16.h>

#define N_NODES 100000
#define N_EDGES 1600000
#define D 128
#define ALPHA 0.5f
#define TILE_NODES 32
#define N_TILES (N_NODES / TILE_NODES)   // 3125 exact
#define WPAD 132                          // conflict-free LDS.128 per quarter-warp phase

// -------- static device scratch --------
__device__ __half g_y_src[(size_t)N_NODES * D];  // dinv_in[n] * (x @ (a*Ws)^T)[n]
__device__ __half g_y_dst[(size_t)N_NODES * D];  // dinv_out[n] * (x @ ((1-a)*Wd)^T)[n]
__device__ float g_cnt_row[N_NODES], g_cnt_col[N_NODES];
__device__ float g_dinv_out[N_NODES], g_dinv_in[N_NODES];
__device__ int   g_is64;

__device__ __forceinline__ int ldidx(const void* p, long long i, int is64) {
  if (is64) return (int)((const long long*)p)[i];
  return ((const int*)p)[i];
}
__device__ __forceinline__ unsigned long long ffma2(
    unsigned long long a, unsigned long long b, unsigned long long c) {
  unsigned long long d;
  asm("fma.rn.f32x2 %0, %1, %2, %3;" : "=l"(d) : "l"(a), "l"(b), "l"(c));
  return d;
}
__device__ __forceinline__ float unpack_sum(unsigned long long a) {
  return __uint_as_float((unsigned)a) + __uint_as_float((unsigned)(a >> 32));
}
__device__ __forceinline__ void cp_async16(void* smem_dst, const void* gsrc) {
  unsigned sa = (unsigned)__cvta_generic_to_shared(smem_dst);
  asm volatile("cp.async.ca.shared.global [%0], [%1], 16;" :: "r"(sa), "l"(gsrc));
}

// -------- 1: zero degree counts + detect index dtype --------
__global__ void k_prep(const void* ei) {
  long long i = (long long)blockIdx.x * blockDim.x + threadIdx.x;
  if (i == 0) {
    const long long* p = (const long long*)ei;
    int ok = 1;
#pragma unroll
    for (int j = 0; j < 16; j++) {
      long long v = p[j];
      if (v < 0 || v >= N_NODES) ok = 0;
    }
    g_is64 = ok;
  }
  if (i < N_NODES) { g_cnt_row[i] = 0.f; g_cnt_col[i] = 0.f; }
}

// -------- 2: degree histograms --------
__global__ void k_degree(const void* ei) {
  long long e = (long long)blockIdx.x * blockDim.x + threadIdx.x;
  if (e >= N_EDGES) return;
  int is64 = g_is64;
  int r = ldidx(ei, e, is64);
  int c = ldidx(ei, (long long)N_EDGES + e, is64);
  atomicAdd(&g_cnt_row[r], 1.f);
  atomicAdd(&g_cnt_col[c], 1.f);
}

// -------- 3: transform, double-buffered x tiles via cp.async --------
__global__ void __launch_bounds__(512, 1) k_transform(
    const float* __restrict__ x,
    const float* __restrict__ W_src, const float* __restrict__ b_src,
    const float* __restrict__ W_dst, const float* __restrict__ b_dst,
    float* __restrict__ out) {
  extern __shared__ float smem[];
  float* Ws = smem;                      // [128][WPAD], scaled by ALPHA
  float* Wd = Ws + D * WPAD;             // scaled by 1-ALPHA
  float* xs0 = Wd + D * WPAD;            // ping [32][128]
  float* xs1 = xs0 + TILE_NODES * D;     // pong

  int tid = threadIdx.x;
  for (int idx = tid; idx < D * D; idx += 512) {
    int d = idx >> 7, k = idx & 127;
    Ws[d * WPAD + k] = ALPHA * W_src[idx];
    Wd[d * WPAD + k] = (1.f - ALPHA) * W_dst[idx];
  }
  int d = tid & 127;
  int q = tid >> 7;                      // quarter handles 8 nodes
  float bias = ALPHA * b_src[d] + (1.f - ALPHA) * b_dst[d];

  const ulonglong2* wsp = (const ulonglong2*)(Ws + d * WPAD);
  const ulonglong2* wdp = (const ulonglong2*)(Wd + d * WPAD);

  // prologue: stage first tile into xs0
  {
    long long base = (long long)blockIdx.x * TILE_NODES;
    cp_async16(xs0 + tid * 4, x + base * D + tid * 4);   // 512 thr x 16B = 8KB
    cp_async16(xs0 + 2048 + tid * 4, x + base * D + 2048 + tid * 4);
    asm volatile("cp.async.commit_group;");
  }

  int p = 0;
  for (int tile = blockIdx.x; tile < N_TILES; tile += gridDim.x) {
    long long base = (long long)tile * TILE_NODES;
    float* xsr = p ? xs1 : xs0;
    float* xsw = p ? xs0 : xs1;

    asm volatile("cp.async.wait_group 0;");
    __syncthreads();                      // xsr full; xsw free (synced last iter)

    int next = tile + gridDim.x;
    if (next < N_TILES) {                 // prefetch next tile into xsw
      long long nb = (long long)next * TILE_NODES * D;
      cp_async16(xsw + tid * 4, x + nb + tid * 4);
      cp_async16(xsw + 2048 + tid * 4, x + nb + 2048 + tid * 4);
      asm volatile("cp.async.commit_group;");
    }

    unsigned long long acc_s[8], acc_d[8];
#pragma unroll
    for (int i = 0; i < 8; i++) { acc_s[i] = 0ull; acc_d[i] = 0ull; }

    const ulonglong2* xrow = (const ulonglong2*)(xsr + (q * 8) * D);
#pragma unroll 4
    for (int kg = 0; kg < 32; kg++) {
      ulonglong2 ws = wsp[kg];
      ulonglong2 wd = wdp[kg];
#pragma unroll
      for (int i = 0; i < 8; i++) {
        ulonglong2 xv = xrow[i * 32 + kg];     // broadcast LDS.128
        acc_s[i] = ffma2(xv.x, ws.x, acc_s[i]);
        acc_s[i] = ffma2(xv.y, ws.y, acc_s[i]);
        acc_d[i] = ffma2(xv.x, wd.x, acc_d[i]);
        acc_d[i] = ffma2(xv.y, wd.y, acc_d[i]);
      }
    }

#pragma unroll
    for (int i = 0; i < 8; i++) {
      long long node = base + q * 8 + i;
      float cr = g_cnt_row[node], cc = g_cnt_col[node];
      float dout = cr > 0.f ? rsqrtf(cr) : 0.f;
      float di   = cc > 0.f ? rsqrtf(cc) : 0.f;
      g_y_src[node * D + d] = __float2half_rn(di   * unpack_sum(acc_s[i]));
      g_y_dst[node * D + d] = __float2half_rn(dout * unpack_sum(acc_d[i]));
      out[node * D + d] = bias;
      if (d == 0) { g_dinv_out[node] = dout; g_dinv_in[node] = di; }
    }
    __syncthreads();                      // done reading xsr
    p ^= 1;
  }
}

// -------- 4: combined edge scatter, 4 edges per warp (MLP=8) --------
__device__ __forceinline__ void red_add_f4(float* p, float a, float b, float c, float d) {
  asm volatile("red.global.add.v4.f32 [%0], {%1, %2, %3, %4};"
               :: "l"(p), "f"(a), "f"(b), "f"(c), "f"(d) : "memory");
}

#define EPW 4   // edges per warp
__global__ void k_scatter(const void* ei, float* __restrict__ out) {
  int lane = threadIdx.x & 31;
  long long ebase = ((long long)blockIdx.x * 8 + (threadIdx.x >> 5)) * EPW;
  int is64 = g_is64;

  int r[EPW], c[EPW];
#pragma unroll
  for (int j = 0; j < EPW; j++) {
    r[j] = ldidx(ei, ebase + j, is64);
    c[j] = ldidx(ei, (long long)N_EDGES + ebase + j, is64);
  }
  float wr[EPW], wc[EPW];
#pragma unroll
  for (int j = 0; j < EPW; j++) {
    wr[j] = g_dinv_out[r[j]];
    wc[j] = g_dinv_in[c[j]];
  }
  uint2 a[EPW], b[EPW];
#pragma unroll
  for (int j = 0; j < EPW; j++) {        // 8 independent 256B-coalesced loads
    a[j] = ((const uint2*)g_y_src)[(long long)c[j] * 32 + lane];
    b[j] = ((const uint2*)g_y_dst)[(long long)r[j] * 32 + lane];
  }
#pragma unroll
  for (int j = 0; j < EPW; j++) {
    float2 a0 = __half22float2(*(const __half2*)&a[j].x);
    float2 a1 = __half22float2(*(const __half2*)&a[j].y);
    red_add_f4(out + (long long)r[j] * D + lane * 4,
               wr[j] * a0.x, wr[j] * a0.y, wr[j] * a1.x, wr[j] * a1.y);
    float2 b0 = __half22float2(*(const __half2*)&b[j].x);
    float2 b1 = __half22float2(*(const __half2*)&b[j].y);
    red_add_f4(out + (long long)c[j] * D + lane * 4,
               wc[j] * b0.x, wc[j] * b0.y, wc[j] * b1.x, wc[j] * b1.y);
  }
}

// -------- launch --------
extern "C" void kernel_launch(void* const* d_in, const int* in_sizes, int n_in,
                              void* d_out, int out_size) {
  const float* x     = (const float*)d_in[0];
  const void*  ei    = d_in[1];
  const float* W_src = (const float*)d_in[2];
  const float* b_src = (const float*)d_in[3];
  const float* W_dst = (const float*)d_in[4];
  const float* b_dst = (const float*)d_in[5];
  float* out = (float*)d_out;

  k_prep  <<<(N_NODES + 255) / 256, 256>>>(ei);
  k_degree<<<(N_EDGES + 255) / 256, 256>>>(ei);

  size_t smem_bytes = (size_t)(2 * D * WPAD + 2 * TILE_NODES * D) * sizeof(float);
  cudaFuncSetAttribute(k_transform, cudaFuncAttributeMaxDynamicSharedMemorySize,
                       (int)smem_bytes);
  k_transform<<<152, 512, smem_bytes>>>(x, W_src, b_src, W_dst, b_dst, out);

  k_scatter<<<N_EDGES / (8 * EPW), 256>>>(ei, out);   // 1.6M % 32 == 0
}

// round 10
// speedup vs baseline: 1.9044x; 1.2658x over previous
#include <cuda_runtime.h>
#include <cuda_fp16.h>

#define N_NODES 100000
#define N_EDGES 1600000
#define D 128
#define ALPHA 0.5f
#define TILE_NODES 32
#define N_TILES (N_NODES / TILE_NODES)   // 3125 exact
#define WPAD 132
#define SCAN_B 1024
#define SCAN_NB ((N_NODES + SCAN_B - 1) / SCAN_B)   // 98

// -------- static device scratch --------
__device__ __half g_y_src[(size_t)N_NODES * D];  // dinv_in[n] * (x @ (a*Ws)^T)[n]
__device__ __half g_y_dst[(size_t)N_NODES * D];  // dinv_out[n] * (x @ ((1-a)*Wd)^T)[n]
__device__ int   g_cnt_row[N_NODES], g_cnt_col[N_NODES];
__device__ int   g_off_row[N_NODES], g_off_col[N_NODES];
__device__ int   g_cur_row[N_NODES], g_cur_col[N_NODES];
__device__ int   g_part_row[SCAN_NB], g_part_col[SCAN_NB];
__device__ float g_dinv_out[N_NODES], g_dinv_in[N_NODES];
__device__ int   g_sorted_col[N_EDGES];   // edges sorted by row; stores col
__device__ int   g_sorted_row[N_EDGES];   // edges sorted by col; stores row
__device__ int   g_is64;

__device__ __forceinline__ int ldidx(const void* p, long long i, int is64) {
  if (is64) return (int)((const long long*)p)[i];
  return ((const int*)p)[i];
}
__device__ __forceinline__ unsigned long long ffma2(
    unsigned long long a, unsigned long long b, unsigned long long c) {
  unsigned long long d;
  asm("fma.rn.f32x2 %0, %1, %2, %3;" : "=l"(d) : "l"(a), "l"(b), "l"(c));
  return d;
}
__device__ __forceinline__ float unpack_sum(unsigned long long a) {
  return __uint_as_float((unsigned)a) + __uint_as_float((unsigned)(a >> 32));
}
__device__ __forceinline__ void cp_async16(void* smem_dst, const void* gsrc) {
  unsigned sa = (unsigned)__cvta_generic_to_shared(smem_dst);
  asm volatile("cp.async.ca.shared.global [%0], [%1], 16;" :: "r"(sa), "l"(gsrc));
}

// -------- 1: zero counts + detect index dtype --------
__global__ void k_prep(const void* ei) {
  long long i = (long long)blockIdx.x * blockDim.x + threadIdx.x;
  if (i == 0) {
    const long long* p = (const long long*)ei;
    int ok = 1;
#pragma unroll
    for (int j = 0; j < 16; j++) {
      long long v = p[j];
      if (v < 0 || v >= N_NODES) ok = 0;
    }
    g_is64 = ok;
  }
  if (i < N_NODES) { g_cnt_row[i] = 0; g_cnt_col[i] = 0; }
}

// -------- 2: degree histograms --------
__global__ void k_hist(const void* ei) {
  long long e = (long long)blockIdx.x * blockDim.x + threadIdx.x;
  if (e >= N_EDGES) return;
  int is64 = g_is64;
  int r = ldidx(ei, e, is64);
  int c = ldidx(ei, (long long)N_EDGES + e, is64);
  atomicAdd(&g_cnt_row[r], 1);
  atomicAdd(&g_cnt_col[c], 1);
}

// -------- 3: blockwise exclusive scan (both histograms) --------
__global__ void k_scan_blocks() {
  __shared__ int sh[SCAN_B];
  int b = blockIdx.x, t = threadIdx.x;
  int gi = b * SCAN_B + t;

  int v = (gi < N_NODES) ? g_cnt_row[gi] : 0;
  sh[t] = v; __syncthreads();
  for (int o = 1; o < SCAN_B; o <<= 1) {
    int x = (t >= o) ? sh[t - o] : 0;
    __syncthreads(); sh[t] += x; __syncthreads();
  }
  if (gi < N_NODES) g_off_row[gi] = sh[t] - v;
  if (t == SCAN_B - 1) g_part_row[b] = sh[t];
  __syncthreads();

  v = (gi < N_NODES) ? g_cnt_col[gi] : 0;
  sh[t] = v; __syncthreads();
  for (int o = 1; o < SCAN_B; o <<= 1) {
    int x = (t >= o) ? sh[t - o] : 0;
    __syncthreads(); sh[t] += x; __syncthreads();
  }
  if (gi < N_NODES) g_off_col[gi] = sh[t] - v;
  if (t == SCAN_B - 1) g_part_col[b] = sh[t];
}

// -------- 4: scan the block totals --------
__global__ void k_scan_tops() {
  __shared__ int sh[128];
  int t = threadIdx.x;
  int v = (t < SCAN_NB) ? g_part_row[t] : 0;
  sh[t] = v; __syncthreads();
  for (int o = 1; o < 128; o <<= 1) {
    int x = (t >= o) ? sh[t - o] : 0;
    __syncthreads(); sh[t] += x; __syncthreads();
  }
  if (t < SCAN_NB) g_part_row[t] = sh[t] - v;
  __syncthreads();
  v = (t < SCAN_NB) ? g_part_col[t] : 0;
  sh[t] = v; __syncthreads();
  for (int o = 1; o < 128; o <<= 1) {
    int x = (t >= o) ? sh[t - o] : 0;
    __syncthreads(); sh[t] += x; __syncthreads();
  }
  if (t < SCAN_NB) g_part_col[t] = sh[t] - v;
}

// -------- 5: finalize offsets, init cursors, compute dinv --------
__global__ void k_scan_add() {
  int b = blockIdx.x, t = threadIdx.x;
  int gi = b * SCAN_B + t;
  if (gi >= N_NODES) return;
  int orow = g_off_row[gi] + g_part_row[b];
  int ocol = g_off_col[gi] + g_part_col[b];
  g_off_row[gi] = orow; g_cur_row[gi] = orow;
  g_off_col[gi] = ocol; g_cur_col[gi] = ocol;
  int cr = g_cnt_row[gi], cc = g_cnt_col[gi];
  g_dinv_out[gi] = cr > 0 ? rsqrtf((float)cr) : 0.f;
  g_dinv_in[gi]  = cc > 0 ? rsqrtf((float)cc) : 0.f;
}

// -------- 6: build CSR (counting-sort scatter) --------
__global__ void k_build(const void* ei) {
  long long e = (long long)blockIdx.x * blockDim.x + threadIdx.x;
  if (e >= N_EDGES) return;
  int is64 = g_is64;
  int r = ldidx(ei, e, is64);
  int c = ldidx(ei, (long long)N_EDGES + e, is64);
  int p = atomicAdd(&g_cur_row[r], 1);
  g_sorted_col[p] = c;
  int q = atomicAdd(&g_cur_col[c], 1);
  g_sorted_row[q] = r;
}

// -------- 7: transform, double-buffered, fp16 prescaled output --------
__global__ void __launch_bounds__(512, 1) k_transform(
    const float* __restrict__ x,
    const float* __restrict__ W_src,
    const float* __restrict__ W_dst) {
  extern __shared__ float smem[];
  float* Ws = smem;
  float* Wd = Ws + D * WPAD;
  float* xs0 = Wd + D * WPAD;
  float* xs1 = xs0 + TILE_NODES * D;

  int tid = threadIdx.x;
  for (int idx = tid; idx < D * D; idx += 512) {
    int d = idx >> 7, k = idx & 127;
    Ws[d * WPAD + k] = ALPHA * W_src[idx];
    Wd[d * WPAD + k] = (1.f - ALPHA) * W_dst[idx];
  }
  int d = tid & 127;
  int q = tid >> 7;

  const ulonglong2* wsp = (const ulonglong2*)(Ws + d * WPAD);
  const ulonglong2* wdp = (const ulonglong2*)(Wd + d * WPAD);

  {
    long long base = (long long)blockIdx.x * TILE_NODES;
    cp_async16(xs0 + tid * 4, x + base * D + tid * 4);
    cp_async16(xs0 + 2048 + tid * 4, x + base * D + 2048 + tid * 4);
    asm volatile("cp.async.commit_group;");
  }

  int p = 0;
  for (int tile = blockIdx.x; tile < N_TILES; tile += gridDim.x) {
    long long base = (long long)tile * TILE_NODES;
    float* xsr = p ? xs1 : xs0;
    float* xsw = p ? xs0 : xs1;

    asm volatile("cp.async.wait_group 0;");
    __syncthreads();

    int next = tile + gridDim.x;
    if (next < N_TILES) {
      long long nb = (long long)next * TILE_NODES * D;
      cp_async16(xsw + tid * 4, x + nb + tid * 4);
      cp_async16(xsw + 2048 + tid * 4, x + nb + 2048 + tid * 4);
      asm volatile("cp.async.commit_group;");
    }

    unsigned long long acc_s[8], acc_d[8];
#pragma unroll
    for (int i = 0; i < 8; i++) { acc_s[i] = 0ull; acc_d[i] = 0ull; }

    const ulonglong2* xrow = (const ulonglong2*)(xsr + (q * 8) * D);
#pragma unroll 4
    for (int kg = 0; kg < 32; kg++) {
      ulonglong2 ws = wsp[kg];
      ulonglong2 wd = wdp[kg];
#pragma unroll
      for (int i = 0; i < 8; i++) {
        ulonglong2 xv = xrow[i * 32 + kg];
        acc_s[i] = ffma2(xv.x, ws.x, acc_s[i]);
        acc_s[i] = ffma2(xv.y, ws.y, acc_s[i]);
        acc_d[i] = ffma2(xv.x, wd.x, acc_d[i]);
        acc_d[i] = ffma2(xv.y, wd.y, acc_d[i]);
      }
    }

#pragma unroll
    for (int i = 0; i < 8; i++) {
      long long node = base + q * 8 + i;
      float di   = g_dinv_in[node];    // L2-hot (written by k_scan_add)
      float dout = g_dinv_out[node];
      g_y_src[node * D + d] = __float2half_rn(di   * unpack_sum(acc_s[i]));
      g_y_dst[node * D + d] = __float2half_rn(dout * unpack_sum(acc_d[i]));
    }
    __syncthreads();
    p ^= 1;
  }
}

// -------- 8: gather — warp per node, 4-way MLP inner loop, single out write --------
__device__ __forceinline__ void acc_row(float4& acc, const uint2 v) {
  float2 v0 = __half22float2(*(const __half2*)&v.x);
  float2 v1 = __half22float2(*(const __half2*)&v.y);
  acc.x += v0.x; acc.y += v0.y; acc.z += v1.x; acc.w += v1.y;
}

__global__ void __launch_bounds__(256, 4) k_gather(
    float* __restrict__ out,
    const float* __restrict__ b_src, const float* __restrict__ b_dst) {
  int lane = threadIdx.x & 31;
  int node = (blockIdx.x * blockDim.x + threadIdx.x) >> 5;
  if (node >= N_NODES) return;

  float4 accf = make_float4(0.f, 0.f, 0.f, 0.f);
  float4 accb = make_float4(0.f, 0.f, 0.f, 0.f);
  const unsigned FULL = 0xffffffffu;

  // forward: sum y_src'[c] over out-neighbors c of node
  {
    int s = g_off_row[node], cnt = g_cnt_row[node];
    for (int bse = 0; bse < cnt; bse += 32) {
      int n = min(32, cnt - bse);
      int idx = (lane < n) ? g_sorted_col[s + bse + lane] : 0;
      int j = 0;
      for (; j + 4 <= n; j += 4) {
        int i0 = __shfl_sync(FULL, idx, j);
        int i1 = __shfl_sync(FULL, idx, j + 1);
        int i2 = __shfl_sync(FULL, idx, j + 2);
        int i3 = __shfl_sync(FULL, idx, j + 3);
        uint2 v0 = ((const uint2*)g_y_src)[(long long)i0 * 32 + lane];
        uint2 v1 = ((const uint2*)g_y_src)[(long long)i1 * 32 + lane];
        uint2 v2 = ((const uint2*)g_y_src)[(long long)i2 * 32 + lane];
        uint2 v3 = ((const uint2*)g_y_src)[(long long)i3 * 32 + lane];
        acc_row(accf, v0); acc_row(accf, v1); acc_row(accf, v2); acc_row(accf, v3);
      }
      for (; j < n; j++) {
        int i0 = __shfl_sync(FULL, idx, j);
        uint2 v0 = ((const uint2*)g_y_src)[(long long)i0 * 32 + lane];
        acc_row(accf, v0);
      }
    }
  }
  // backward: sum y_dst'[r] over in-neighbors r of node
  {
    int s = g_off_col[node], cnt = g_cnt_col[node];
    for (int bse = 0; bse < cnt; bse += 32) {
      int n = min(32, cnt - bse);
      int idx = (lane < n) ? g_sorted_row[s + bse + lane] : 0;
      int j = 0;
      for (; j + 4 <= n; j += 4) {
        int i0 = __shfl_sync(FULL, idx, j);
        int i1 = __shfl_sync(FULL, idx, j + 1);
        int i2 = __shfl_sync(FULL, idx, j + 2);
        int i3 = __shfl_sync(FULL, idx, j + 3);
        uint2 v0 = ((const uint2*)g_y_dst)[(long long)i0 * 32 + lane];
        uint2 v1 = ((const uint2*)g_y_dst)[(long long)i1 * 32 + lane];
        uint2 v2 = ((const uint2*)g_y_dst)[(long long)i2 * 32 + lane];
        uint2 v3 = ((const uint2*)g_y_dst)[(long long)i3 * 32 + lane];
        acc_row(accb, v0); acc_row(accb, v1); acc_row(accb, v2); acc_row(accb, v3);
      }
      for (; j < n; j++) {
        int i0 = __shfl_sync(FULL, idx, j);
        uint2 v0 = ((const uint2*)g_y_dst)[(long long)i0 * 32 + lane];
        acc_row(accb, v0);
      }
    }
  }

  float dout = g_dinv_out[node];
  float di   = g_dinv_in[node];
  int bidx = lane * 4;
  float4 o;
  o.x = ALPHA * b_src[bidx+0] + (1.f-ALPHA) * b_dst[bidx+0] + dout * accf.x + di * accb.x;
  o.y = ALPHA * b_src[bidx+1] + (1.f-ALPHA) * b_dst[bidx+1] + dout * accf.y + di * accb.y;
  o.z = ALPHA * b_src[bidx+2] + (1.f-ALPHA) * b_dst[bidx+2] + dout * accf.z + di * accb.z;
  o.w = ALPHA * b_src[bidx+3] + (1.f-ALPHA) * b_dst[bidx+3] + dout * accf.w + di * accb.w;
  ((float4*)(out + (long long)node * D))[lane] = o;
}

// -------- launch --------
extern "C" void kernel_launch(void* const* d_in, const int* in_sizes, int n_in,
                              void* d_out, int out_size) {
  const float* x     = (const float*)d_in[0];
  const void*  ei    = d_in[1];
  const float* W_src = (const float*)d_in[2];
  const float* b_src = (const float*)d_in[3];
  const float* W_dst = (const float*)d_in[4];
  const float* b_dst = (const float*)d_in[5];
  float* out = (float*)d_out;

  k_prep<<<(N_NODES + 255) / 256, 256>>>(ei);
  k_hist<<<(N_EDGES + 255) / 256, 256>>>(ei);
  k_scan_blocks<<<SCAN_NB, SCAN_B>>>();
  k_scan_tops<<<1, 128>>>();
  k_scan_add<<<SCAN_NB, SCAN_B>>>();
  k_build<<<(N_EDGES + 255) / 256, 256>>>(ei);

  size_t smem_bytes = (size_t)(2 * D * WPAD + 2 * TILE_NODES * D) * sizeof(float);
  cudaFuncSetAttribute(k_transform, cudaFuncAttributeMaxDynamicSharedMemorySize,
                       (int)smem_bytes);
  k_transform<<<152, 512, smem_bytes>>>(x, W_src, W_dst);

  k_gather<<<(N_NODES * 32 + 255) / 256, 256>>>(out, b_src, b_dst);
}

// round 11
// speedup vs baseline: 2.0170x; 1.0591x over previous
#include <cuda_runtime.h>
#include <cuda_fp16.h>

#define N_NODES 100000
#define N_EDGES 1600000
#define D 128
#define ALPHA 0.5f
#define TILE_NODES 32
#define N_TILES (N_NODES / TILE_NODES)   // 3125 exact
#define WPAD 132
#define SCAN_B 1024
#define SCAN_NB ((N_NODES + SCAN_B - 1) / SCAN_B)   // 98

// -------- static device scratch --------
__device__ __half g_y_src[(size_t)N_NODES * D];  // dinv_in[n] * (x @ (a*Ws)^T)[n]
__device__ __half g_y_dst[(size_t)N_NODES * D];  // dinv_out[n] * (x @ ((1-a)*Wd)^T)[n]
__device__ int   g_cnt_row[N_NODES], g_cnt_col[N_NODES];
__device__ int   g_off_row[N_NODES], g_off_col[N_NODES];   // block-LOCAL exclusive offsets
__device__ int   g_cur_row[N_NODES], g_cur_col[N_NODES];   // cursors (local)
__device__ int   g_part_row[SCAN_NB], g_part_col[SCAN_NB]; // per-block bases after tops-scan
__device__ float g_dinv_out[N_NODES], g_dinv_in[N_NODES];
__device__ int   g_sorted_col[N_EDGES];   // edges sorted by row; stores col
__device__ int   g_sorted_row[N_EDGES];   // edges sorted by col; stores row
__device__ int   g_is64;

__device__ __forceinline__ int ldidx(const void* p, long long i, int is64) {
  if (is64) return (int)((const long long*)p)[i];
  return ((const int*)p)[i];
}
__device__ __forceinline__ unsigned long long ffma2(
    unsigned long long a, unsigned long long b, unsigned long long c) {
  unsigned long long d;
  asm("fma.rn.f32x2 %0, %1, %2, %3;" : "=l"(d) : "l"(a), "l"(b), "l"(c));
  return d;
}
__device__ __forceinline__ float unpack_sum(unsigned long long a) {
  return __uint_as_float((unsigned)a) + __uint_as_float((unsigned)(a >> 32));
}
__device__ __forceinline__ void cp_async16(void* smem_dst, const void* gsrc) {
  unsigned sa = (unsigned)__cvta_generic_to_shared(smem_dst);
  asm volatile("cp.async.ca.shared.global [%0], [%1], 16;" :: "r"(sa), "l"(gsrc));
}

// -------- 1: zero counts + detect index dtype --------
__global__ void k_prep(const void* ei) {
  long long i = (long long)blockIdx.x * blockDim.x + threadIdx.x;
  if (i == 0) {
    const long long* p = (const long long*)ei;
    int ok = 1;
#pragma unroll
    for (int j = 0; j < 16; j++) {
      long long v = p[j];
      if (v < 0 || v >= N_NODES) ok = 0;
    }
    g_is64 = ok;
  }
  if (i < N_NODES) { g_cnt_row[i] = 0; g_cnt_col[i] = 0; }
}

// -------- 2: degree histograms --------
__global__ void k_hist(const void* ei) {
  long long e = (long long)blockIdx.x * blockDim.x + threadIdx.x;
  if (e >= N_EDGES) return;
  int is64 = g_is64;
  int r = ldidx(ei, e, is64);
  int c = ldidx(ei, (long long)N_EDGES + e, is64);
  atomicAdd(&g_cnt_row[r], 1);
  atomicAdd(&g_cnt_col[c], 1);
}

// -------- 3: blockwise exclusive scan; init cursors to local offsets --------
__global__ void k_scan_blocks() {
  __shared__ int sh[SCAN_B];
  int b = blockIdx.x, t = threadIdx.x;
  int gi = b * SCAN_B + t;

  int v = (gi < N_NODES) ? g_cnt_row[gi] : 0;
  sh[t] = v; __syncthreads();
  for (int o = 1; o < SCAN_B; o <<= 1) {
    int x = (t >= o) ? sh[t - o] : 0;
    __syncthreads(); sh[t] += x; __syncthreads();
  }
  if (gi < N_NODES) { g_off_row[gi] = sh[t] - v; g_cur_row[gi] = sh[t] - v; }
  if (t == SCAN_B - 1) g_part_row[b] = sh[t];
  __syncthreads();

  v = (gi < N_NODES) ? g_cnt_col[gi] : 0;
  sh[t] = v; __syncthreads();
  for (int o = 1; o < SCAN_B; o <<= 1) {
    int x = (t >= o) ? sh[t - o] : 0;
    __syncthreads(); sh[t] += x; __syncthreads();
  }
  if (gi < N_NODES) { g_off_col[gi] = sh[t] - v; g_cur_col[gi] = sh[t] - v; }
  if (t == SCAN_B - 1) g_part_col[b] = sh[t];
}

// -------- 4: exclusive-scan the block totals --------
__global__ void k_scan_tops() {
  __shared__ int sh[128];
  int t = threadIdx.x;
  int v = (t < SCAN_NB) ? g_part_row[t] : 0;
  sh[t] = v; __syncthreads();
  for (int o = 1; o < 128; o <<= 1) {
    int x = (t >= o) ? sh[t - o] : 0;
    __syncthreads(); sh[t] += x; __syncthreads();
  }
  if (t < SCAN_NB) g_part_row[t] = sh[t] - v;
  __syncthreads();
  v = (t < SCAN_NB) ? g_part_col[t] : 0;
  sh[t] = v; __syncthreads();
  for (int o = 1; o < 128; o <<= 1) {
    int x = (t >= o) ? sh[t - o] : 0;
    __syncthreads(); sh[t] += x; __syncthreads();
  }
  if (t < SCAN_NB) g_part_col[t] = sh[t] - v;
}

// -------- 5: build CSR (counting sort); final pos = local cursor + block base --------
__global__ void k_build(const void* ei) {
  long long e = (long long)blockIdx.x * blockDim.x + threadIdx.x;
  if (e >= N_EDGES) return;
  int is64 = g_is64;
  int r = ldidx(ei, e, is64);
  int c = ldidx(ei, (long long)N_EDGES + e, is64);
  int p = atomicAdd(&g_cur_row[r], 1) + g_part_row[r >> 10];
  g_sorted_col[p] = c;
  int q = atomicAdd(&g_cur_col[c], 1) + g_part_col[c >> 10];
  g_sorted_row[q] = r;
}

// -------- 6: transform (runs CONCURRENT with 3-5 on another stream) --------
__global__ void __launch_bounds__(512, 1) k_transform(
    const float* __restrict__ x,
    const float* __restrict__ W_src,
    const float* __restrict__ W_dst) {
  extern __shared__ float smem[];
  float* Ws = smem;
  float* Wd = Ws + D * WPAD;
  float* xs0 = Wd + D * WPAD;
  float* xs1 = xs0 + TILE_NODES * D;

  int tid = threadIdx.x;
  for (int idx = tid; idx < D * D; idx += 512) {
    int d = idx >> 7, k = idx & 127;
    Ws[d * WPAD + k] = ALPHA * W_src[idx];
    Wd[d * WPAD + k] = (1.f - ALPHA) * W_dst[idx];
  }
  int d = tid & 127;
  int q = tid >> 7;

  const ulonglong2* wsp = (const ulonglong2*)(Ws + d * WPAD);
  const ulonglong2* wdp = (const ulonglong2*)(Wd + d * WPAD);

  {
    long long base = (long long)blockIdx.x * TILE_NODES;
    cp_async16(xs0 + tid * 4, x + base * D + tid * 4);
    cp_async16(xs0 + 2048 + tid * 4, x + base * D + 2048 + tid * 4);
    asm volatile("cp.async.commit_group;");
  }

  int p = 0;
  for (int tile = blockIdx.x; tile < N_TILES; tile += gridDim.x) {
    long long base = (long long)tile * TILE_NODES;
    float* xsr = p ? xs1 : xs0;
    float* xsw = p ? xs0 : xs1;

    asm volatile("cp.async.wait_group 0;");
    __syncthreads();

    int next = tile + gridDim.x;
    if (next < N_TILES) {
      long long nb = (long long)next * TILE_NODES * D;
      cp_async16(xsw + tid * 4, x + nb + tid * 4);
      cp_async16(xsw + 2048 + tid * 4, x + nb + 2048 + tid * 4);
      asm volatile("cp.async.commit_group;");
    }

    unsigned long long acc_s[8], acc_d[8];
#pragma unroll
    for (int i = 0; i < 8; i++) { acc_s[i] = 0ull; acc_d[i] = 0ull; }

    const ulonglong2* xrow = (const ulonglong2*)(xsr + (q * 8) * D);
#pragma unroll 4
    for (int kg = 0; kg < 32; kg++) {
      ulonglong2 ws = wsp[kg];
      ulonglong2 wd = wdp[kg];
#pragma unroll
      for (int i = 0; i < 8; i++) {
        ulonglong2 xv = xrow[i * 32 + kg];
        acc_s[i] = ffma2(xv.x, ws.x, acc_s[i]);
        acc_s[i] = ffma2(xv.y, ws.y, acc_s[i]);
        acc_d[i] = ffma2(xv.x, wd.x, acc_d[i]);
        acc_d[i] = ffma2(xv.y, wd.y, acc_d[i]);
      }
    }

#pragma unroll
    for (int i = 0; i < 8; i++) {
      long long node = base + q * 8 + i;
      int cr = g_cnt_row[node];          // L2-hot after k_hist; broadcast LDG
      int cc = g_cnt_col[node];
      float dout = cr > 0 ? rsqrtf((float)cr) : 0.f;
      float di   = cc > 0 ? rsqrtf((float)cc) : 0.f;
      g_y_src[node * D + d] = __float2half_rn(di   * unpack_sum(acc_s[i]));
      g_y_dst[node * D + d] = __float2half_rn(dout * unpack_sum(acc_d[i]));
      if (d == 0) { g_dinv_out[node] = dout; g_dinv_in[node] = di; }
    }
    __syncthreads();
    p ^= 1;
  }
}

// -------- 7: gather — warp per node, 4-way MLP inner loop, single out write --------
__device__ __forceinline__ void acc_row(float4& acc, const uint2 v) {
  float2 v0 = __half22float2(*(const __half2*)&v.x);
  float2 v1 = __half22float2(*(const __half2*)&v.y);
  acc.x += v0.x; acc.y += v0.y; acc.z += v1.x; acc.w += v1.y;
}

__global__ void __launch_bounds__(256, 4) k_gather(
    float* __restrict__ out,
    const float* __restrict__ b_src, const float* __restrict__ b_dst) {
  int lane = threadIdx.x & 31;
  int node = (blockIdx.x * blockDim.x + threadIdx.x) >> 5;
  if (node >= N_NODES) return;

  float4 accf = make_float4(0.f, 0.f, 0.f, 0.f);
  float4 accb = make_float4(0.f, 0.f, 0.f, 0.f);
  const unsigned FULL = 0xffffffffu;

  {
    int s = g_off_row[node] + g_part_row[node >> 10];
    int cnt = g_cnt_row[node];
    for (int bse = 0; bse < cnt; bse += 32) {
      int n = min(32, cnt - bse);
      int idx = (lane < n) ? g_sorted_col[s + bse + lane] : 0;
      int j = 0;
      for (; j + 4 <= n; j += 4) {
        int i0 = __shfl_sync(FULL, idx, j);
        int i1 = __shfl_sync(FULL, idx, j + 1);
        int i2 = __shfl_sync(FULL, idx, j + 2);
        int i3 = __shfl_sync(FULL, idx, j + 3);
        uint2 v0 = ((const uint2*)g_y_src)[(long long)i0 * 32 + lane];
        uint2 v1 = ((const uint2*)g_y_src)[(long long)i1 * 32 + lane];
        uint2 v2 = ((const uint2*)g_y_src)[(long long)i2 * 32 + lane];
        uint2 v3 = ((const uint2*)g_y_src)[(long long)i3 * 32 + lane];
        acc_row(accf, v0); acc_row(accf, v1); acc_row(accf, v2); acc_row(accf, v3);
      }
      for (; j < n; j++) {
        int i0 = __shfl_sync(FULL, idx, j);
        uint2 v0 = ((const uint2*)g_y_src)[(long long)i0 * 32 + lane];
        acc_row(accf, v0);
      }
    }
  }
  {
    int s = g_off_col[node] + g_part_col[node >> 10];
    int cnt = g_cnt_col[node];
    for (int bse = 0; bse < cnt; bse += 32) {
      int n = min(32, cnt - bse);
      int idx = (lane < n) ? g_sorted_row[s + bse + lane] : 0;
      int j = 0;
      for (; j + 4 <= n; j += 4) {
        int i0 = __shfl_sync(FULL, idx, j);
        int i1 = __shfl_sync(FULL, idx, j + 1);
        int i2 = __shfl_sync(FULL, idx, j + 2);
        int i3 = __shfl_sync(FULL, idx, j + 3);
        uint2 v0 = ((const uint2*)g_y_dst)[(long long)i0 * 32 + lane];
        uint2 v1 = ((const uint2*)g_y_dst)[(long long)i1 * 32 + lane];
        uint2 v2 = ((const uint2*)g_y_dst)[(long long)i2 * 32 + lane];
        uint2 v3 = ((const uint2*)g_y_dst)[(long long)i3 * 32 + lane];
        acc_row(accb, v0); acc_row(accb, v1); acc_row(accb, v2); acc_row(accb, v3);
      }
      for (; j < n; j++) {
        int i0 = __shfl_sync(FULL, idx, j);
        uint2 v0 = ((const uint2*)g_y_dst)[(long long)i0 * 32 + lane];
        acc_row(accb, v0);
      }
    }
  }

  float dout = g_dinv_out[node];
  float di   = g_dinv_in[node];
  int bidx = lane * 4;
  float4 o;
  o.x = ALPHA * b_src[bidx+0] + (1.f-ALPHA) * b_dst[bidx+0] + dout * accf.x + di * accb.x;
  o.y = ALPHA * b_src[bidx+1] + (1.f-ALPHA) * b_dst[bidx+1] + dout * accf.y + di * accb.y;
  o.z = ALPHA * b_src[bidx+2] + (1.f-ALPHA) * b_dst[bidx+2] + dout * accf.z + di * accb.z;
  o.w = ALPHA * b_src[bidx+3] + (1.f-ALPHA) * b_dst[bidx+3] + dout * accf.w + di * accb.w;
  ((float4*)(out + (long long)node * D))[lane] = o;
}

// -------- launch: fork-join so CSR build overlaps transform --------
extern "C" void kernel_launch(void* const* d_in, const int* in_sizes, int n_in,
                              void* d_out, int out_size) {
  const float* x     = (const float*)d_in[0];
  const void*  ei    = d_in[1];
  const float* W_src = (const float*)d_in[2];
  const float* b_src = (const float*)d_in[3];
  const float* W_dst = (const float*)d_in[4];
  const float* b_dst = (const float*)d_in[5];
  float* out = (float*)d_out;

  // Per-call stream/event creation (not device memory; kernel_launch runs only
  // for correctness + capture, replays use the captured graph). Leaked by design.
  cudaStream_t s2;
  cudaStreamCreateWithFlags(&s2, cudaStreamNonBlocking);
  cudaEvent_t evFork, evJoin;
  cudaEventCreateWithFlags(&evFork, cudaEventDisableTiming);
  cudaEventCreateWithFlags(&evJoin, cudaEventDisableTiming);

  k_prep<<<(N_NODES + 255) / 256, 256>>>(ei);
  k_hist<<<(N_EDGES + 255) / 256, 256>>>(ei);

  // fork: CSR build chain on s2, transform on main stream
  cudaEventRecord(evFork, 0);
  cudaStreamWaitEvent(s2, evFork, 0);

  k_scan_blocks<<<SCAN_NB, SCAN_B, 0, s2>>>();
  k_scan_tops<<<1, 128, 0, s2>>>();
  k_build<<<(N_EDGES + 255) / 256, 256, 0, s2>>>(ei);
  cudaEventRecord(evJoin, s2);

  size_t smem_bytes = (size_t)(2 * D * WPAD + 2 * TILE_NODES * D) * sizeof(float);
  cudaFuncSetAttribute(k_transform, cudaFuncAttributeMaxDynamicSharedMemorySize,
                       (int)smem_bytes);
  k_transform<<<152, 512, smem_bytes>>>(x, W_src, W_dst);

  // join: gather needs both y arrays (main) and CSR (s2)
  cudaStreamWaitEvent(0, evJoin, 0);
  k_gather<<<(N_NODES * 32 + 255) / 256, 256>>>(out, b_src, b_dst);
}